// round 8
// baseline (speedup 1.0000x reference)
#include <cuda_runtime.h>
#include <cstdint>
#include <math.h>

// Symmetric Hausdorff distance via uniform-grid nearest-neighbor search.
// B=4, N=M=8192, D=3, fp32. Points ~ N(0,1)^3 -> NN distances << domain size,
// so grid NN does ~250 candidate evals per query instead of 8192.
//
// Grid: 32^3 over [-4,4]^3 (h=0.25). 8 grids (2 sets x 4 batches) share one
// concatenated cell array (262144 cells) and one global counting sort.
// Outliers (|coord|>4, ~1e-4 probability per coord) are clamped to edge cells:
// safe, because clamping moves a point only OUTWARD from its assigned cell, so
// the ring lower bound ((r-1)*h) remains a valid lower bound, and same-cell
// pairs are always evaluated exactly.
//
// Query: expanding Chebyshev shells around the query's cell; stop when
// ((r-1)*h)^2 >= best_d2. Exact d^2 by squared differences. Per-batch result
// via atomicMax on int bits of d^2 (exact & order-independent for d2 >= 0).
// Determinism: cell-internal placement order varies (atomicAdd), but fmin/fmax
// over a set are order-independent, so outputs are bitwise stable.

#define BATCH 4
#define NPB 8192                 // points per (set,batch)
#define TOTPTS (2*BATCH*NPB)     // 65536
#define G 32
#define GC (G*G*G)               // 32768 cells per grid
#define NCELLS (8*GC)            // 262144 total
#define RANGE 4.0f
#define H 0.25f
#define INVH 4.0f
#define FINF_BITS 0x7f800000

__device__ int    g_cnt[NCELLS];
__device__ int    g_p1[NCELLS];    // within-scan-block exclusive prefix
__device__ int    g_bscan[512];    // per-scan-block sums -> exclusive scanned
__device__ int    g_cur[NCELLS];
__device__ float4 g_pts[TOTPTS];   // cell-sorted points
__device__ int    g_res[BATCH];    // max over all per-point min d^2 (int bits)

__device__ __forceinline__ int clampi(int v, int lo, int hi) {
    return v < lo ? lo : (v > hi ? hi : v);
}
__device__ __forceinline__ void cell_coords(float x, float y, float z,
                                            int& cx, int& cy, int& cz) {
    cx = clampi((int)floorf((x + RANGE) * INVH), 0, G - 1);
    cy = clampi((int)floorf((y + RANGE) * INVH), 0, G - 1);
    cz = clampi((int)floorf((z + RANGE) * INVH), 0, G - 1);
}

// Fetch point coords for global point index t (t<32768: pred, else gt).
__device__ __forceinline__ float3 fetch_pt(const float* __restrict__ pred,
                                           const float* __restrict__ gt, int t) {
    const float* s = (t < BATCH * NPB) ? (pred + 3 * (size_t)t)
                                       : (gt + 3 * (size_t)(t - BATCH * NPB));
    return make_float3(s[0], s[1], s[2]);
}

__global__ void k_zero() {
    int i = blockIdx.x * blockDim.x + threadIdx.x;
    if (i < NCELLS) { g_cnt[i] = 0; g_cur[i] = 0; }
    if (i < BATCH) g_res[i] = 0;
}

__global__ void k_count(const float* __restrict__ pred,
                        const float* __restrict__ gt) {
    int t = blockIdx.x * blockDim.x + threadIdx.x;
    if (t >= TOTPTS) return;
    float3 p = fetch_pt(pred, gt, t);
    int cx, cy, cz; cell_coords(p.x, p.y, p.z, cx, cy, cz);
    int si = t >> 13;                       // (set*4 + batch), 0..7
    atomicAdd(&g_cnt[si * GC + (cz << 10) + (cy << 5) + cx], 1);
}

// Per-512-block inclusive scan -> exclusive prefixes + block sums.
__global__ void k_scan1() {
    __shared__ int sh[512];
    const int tid = threadIdx.x;
    const int i = blockIdx.x * 512 + tid;
    int v = g_cnt[i];
    sh[tid] = v; __syncthreads();
    for (int o = 1; o < 512; o <<= 1) {
        int a = (tid >= o) ? sh[tid - o] : 0;
        __syncthreads();
        sh[tid] += a;
        __syncthreads();
    }
    g_p1[i] = sh[tid] - v;                  // exclusive within block
    if (tid == 511) g_bscan[blockIdx.x] = sh[511];
}

// Exclusive scan of the 512 block sums (single block).
__global__ void k_scan2() {
    __shared__ int sh[512];
    const int tid = threadIdx.x;
    int v = g_bscan[tid];
    sh[tid] = v; __syncthreads();
    for (int o = 1; o < 512; o <<= 1) {
        int a = (tid >= o) ? sh[tid - o] : 0;
        __syncthreads();
        sh[tid] += a;
        __syncthreads();
    }
    g_bscan[tid] = sh[tid] - v;             // exclusive
}

__global__ void k_reorder(const float* __restrict__ pred,
                          const float* __restrict__ gt) {
    int t = blockIdx.x * blockDim.x + threadIdx.x;
    if (t >= TOTPTS) return;
    float3 p = fetch_pt(pred, gt, t);
    int cx, cy, cz; cell_coords(p.x, p.y, p.z, cx, cy, cz);
    int si = t >> 13;
    int c = si * GC + (cz << 10) + (cy << 5) + cx;
    int slot = g_p1[c] + g_bscan[c >> 9] + atomicAdd(&g_cur[c], 1);
    g_pts[slot] = make_float4(p.x, p.y, p.z, 0.0f);
}

__device__ __forceinline__ void scan_cell(const float4 q, int c, float& best) {
    int s0 = g_p1[c] + g_bscan[c >> 9];
    int n  = g_cnt[c];
    for (int k = 0; k < n; k++) {
        float4 p = g_pts[s0 + k];
        float dx = q.x - p.x, dy = q.y - p.y, dz = q.z - p.z;
        float d2 = fmaf(dx, dx, fmaf(dy, dy, dz * dz));
        best = fminf(best, d2);
    }
}

__global__ __launch_bounds__(128) void k_query() {
    int t = blockIdx.x * blockDim.x + threadIdx.x;
    if (t >= TOTPTS) return;
    const float4 q = g_pts[t];              // sorted order -> warp locality
    const int si   = t >> 13;               // this point's (set,batch)
    const int base = (si ^ 4) * GC;         // opposite set, same batch
    int qcx, qcy, qcz; cell_coords(q.x, q.y, q.z, qcx, qcy, qcz);

    float best = __int_as_float(FINF_BITS);
    for (int r = 0; r <= G; r++) {
        if (r > 0) {
            float lb = (float)(r - 1) * H;
            if (lb * lb >= best) break;
        }
        int zlo = max(qcz - r, 0), zhi = min(qcz + r, G - 1);
        for (int cz = zlo; cz <= zhi; cz++) {
            bool zface = (cz == qcz - r) || (cz == qcz + r);
            int ylo = max(qcy - r, 0), yhi = min(qcy + r, G - 1);
            for (int cy = ylo; cy <= yhi; cy++) {
                bool yface = (cy == qcy - r) || (cy == qcy + r);
                int rowbase = base + (cz << 10) + (cy << 5);
                if (zface || yface) {
                    int xlo = max(qcx - r, 0), xhi = min(qcx + r, G - 1);
                    for (int cx = xlo; cx <= xhi; cx++)
                        scan_cell(q, rowbase + cx, best);
                } else {
                    if (qcx - r >= 0) scan_cell(q, rowbase + qcx - r, best);
                    if (qcx + r <= G - 1) scan_cell(q, rowbase + qcx + r, best);
                }
            }
        }
    }
    // best = min d^2 over the opposite set (exact). Hausdorff: max over points.
    atomicMax(&g_res[si & 3], __float_as_int(best));
}

__global__ void k_fin(float* __restrict__ out) {
    int b = threadIdx.x;
    if (b < BATCH) out[b] = sqrtf(__int_as_float(g_res[b]));
}

extern "C" void kernel_launch(void* const* d_in, const int* in_sizes, int n_in,
                              void* d_out, int out_size) {
    const float* pred = (const float*)d_in[0];
    const float* gt   = (const float*)d_in[1];
    float* out = (float*)d_out;

    k_zero<<<(NCELLS + 255) / 256, 256>>>();
    k_count<<<TOTPTS / 256, 256>>>(pred, gt);
    k_scan1<<<NCELLS / 512, 512>>>();
    k_scan2<<<1, 512>>>();
    k_reorder<<<TOTPTS / 256, 256>>>(pred, gt);
    k_query<<<TOTPTS / 128, 128>>>();
    k_fin<<<1, BATCH>>>(out);
}

// round 10
// speedup vs baseline: 5.4780x; 5.4780x over previous
#include <cuda_runtime.h>
#include <cstdint>
#include <math.h>

// Symmetric Hausdorff distance, B=4, N=M=8192, D=3, fp32 — threshold-pruned.
//
// A row (query point) cannot be the Hausdorff argmax if its PARTIAL min over
// any subset of targets drops below a lower bound L of the final answer.
// Completed rows' exact mins are such lower bounds, and since the output is
// max(d_xy, d_yx), ONE threshold per batch serves both directions.
//
// k_seed: exact full scans for 256 strided rows per (dir,batch) -> seeds
//         g_res[b] (atomicMax on int bits of d^2 >= 0: exact, order-free).
// k_main: all other rows; warp = row, lanes over targets; every 128 targets a
//         warp REDUX min is compared against g_res[b] (uniform break).
//         The argmax row's partial min is always >= answer >= threshold, so it
//         is never pruned and writes the exact max -> output is exact and
//         bitwise deterministic regardless of pruning timing.
// k_fin:  out[b] = sqrt(g_res[b]); resets g_res for the next graph replay
//         (module-load zero-init covers the very first call).

#define BATCH 4
#define NPB 8192
#define FINF_BITS 0x7f800000

__device__ int g_res[BATCH];   // per-batch running max of completed row mins (d^2 bits)

__device__ __forceinline__ float dist2(float qx, float qy, float qz,
                                       const float* __restrict__ t) {
    float dx = qx - t[0], dy = qy - t[1], dz = qz - t[2];
    return fmaf(dx, dx, fmaf(dy, dy, dz * dz));
}

template <bool PRUNE>
__device__ __forceinline__ void scan_row(const float* __restrict__ q3,
                                         const float* __restrict__ T,
                                         int b, int lane) {
    const float qx = q3[0], qy = q3[1], qz = q3[2];
    float rmin = __int_as_float(FINF_BITS);
    unsigned wm = FINF_BITS;
    for (int j0 = 0; j0 < NPB; j0 += 128) {
#pragma unroll
        for (int s = 0; s < 4; s++) {
            const float* t = T + 3 * (j0 + s * 32 + lane);  // coalesced: 384B/warp
            rmin = fminf(rmin, dist2(qx, qy, qz, t));
        }
        // d^2 >= 0: unsigned bit order == float order.
        wm = __reduce_min_sync(0xffffffffu, (unsigned)__float_as_int(rmin));
        if (PRUNE) {
            int thr = __ldcg(&g_res[b]);                    // stale read only under-prunes
            if (__int_as_float((int)wm) < __int_as_float(thr)) return;  // uniform
        }
    }
    if (lane == 0) atomicMax(&g_res[b], (int)wm);           // exact completed min
}

// Seed: 256 blocks x 256 thr = 2048 warps; rows n = k*32 per (dir,batch).
__global__ __launch_bounds__(256) void k_seed(const float* __restrict__ pred,
                                              const float* __restrict__ gt) {
    const int warp = threadIdx.x >> 5, lane = threadIdx.x & 31;
    const int db = blockIdx.x >> 5;                 // 0..7 = dir*4 + batch
    const int k  = (blockIdx.x & 31) * 8 + warp;    // 0..255
    const int dir = db >> 2, b = db & 3;
    const int n = k * 32;
    const float* Q = dir ? gt : pred;
    const float* T = dir ? pred : gt;
    scan_row<false>(Q + 3 * (size_t)(b * NPB + n), T + 3 * (size_t)b * NPB, b, lane);
}

// Main: 4096 blocks x 512 thr = 65536 warps; one row each; skip seeded rows.
__global__ __launch_bounds__(512) void k_main(const float* __restrict__ pred,
                                              const float* __restrict__ gt) {
    const int warp = threadIdx.x >> 5, lane = threadIdx.x & 31;
    const int db = blockIdx.x >> 9;                        // 0..7
    const int n  = (blockIdx.x & 511) * 16 + warp;         // 0..8191
    if ((n & 31) == 0) return;                             // covered by k_seed
    const int dir = db >> 2, b = db & 3;
    const float* Q = dir ? gt : pred;
    const float* T = dir ? pred : gt;
    scan_row<true>(Q + 3 * (size_t)(b * NPB + n), T + 3 * (size_t)b * NPB, b, lane);
}

__global__ void k_fin(float* __restrict__ out) {
    const int b = threadIdx.x;
    if (b < BATCH) {
        out[b] = sqrtf(__int_as_float(g_res[b]));
        g_res[b] = 0;                                      // reset for next replay
    }
}

extern "C" void kernel_launch(void* const* d_in, const int* in_sizes, int n_in,
                              void* d_out, int out_size) {
    const float* pred = (const float*)d_in[0];
    const float* gt   = (const float*)d_in[1];
    float* out = (float*)d_out;

    k_seed<<<256, 256>>>(pred, gt);
    k_main<<<4096, 512>>>(pred, gt);
    k_fin<<<1, 32>>>(out);
}